// round 5
// baseline (speedup 1.0000x reference)
#include <cuda_runtime.h>
#include <cuda_bf16.h>

#define B_   32
#define N_   4096
#define D_   64
#define BC_  4
#define C_   129

// Scratch (no allocations allowed)
__device__ __align__(16) int g_order[BC_ * N_];
__device__ __align__(16) int g_starts[BC_ * (C_ + 1)];
__device__ __align__(16) float g_Qc[B_ * C_ * D_];
__device__ __align__(16) float g_Kc[B_ * C_ * D_];
__device__ __align__(16) float g_Vc[B_ * C_ * D_];

// ---------------------------------------------------------------------------
// Kernel 1: atomic-free counting sort per cluster-batch. grid 4 x 1024.
// Order within a cluster is irrelevant downstream (sums + broadcasts), so we
// use per-warp privatized histograms + match_any ranking, no atomics at all.
// ---------------------------------------------------------------------------
__global__ void sort_kernel(const void* __restrict__ cl_raw) {
    __shared__ int scl[N_];             // labels for this cluster-batch
    __shared__ int sW[32 * C_];         // per-warp hist -> prefix -> cursor
    __shared__ int sTot[C_];            // per-bin totals
    __shared__ int sStart[C_];          // per-bin starts
    __shared__ int s_bad;

    int bc   = blockIdx.x;
    int t    = threadIdx.x;
    int w    = t >> 5;
    int lane = t & 31;

    if (t == 0) s_bad = 0;
    for (int i = t; i < 32 * C_; i += 1024) sW[i] = 0;
    __syncthreads();

    // dtype detect on own slice: int64 view of int32 data fails range check
    const long long* c64 = (const long long*)cl_raw + (size_t)bc * N_;
    int bad = 0;
#pragma unroll
    for (int r = 0; r < 2; r++) {
        long long v = ((const long long*)((const int*)cl_raw + (size_t)bc * N_))[r * 1024 + t];
        if (v < 0 || v >= C_) bad = 1;
    }
    if (bad) s_bad = 1;     // benign race, write-only flag
    __syncthreads();

    if (s_bad) {
        const int4* c32v = (const int4*)((const int*)cl_raw + (size_t)bc * N_);
        int4 v = c32v[t];
        scl[4 * t + 0] = v.x; scl[4 * t + 1] = v.y;
        scl[4 * t + 2] = v.z; scl[4 * t + 3] = v.w;
    } else {
#pragma unroll
        for (int r = 0; r < 2; r++) {
            longlong2 v = ((const longlong2*)c64)[r * 1024 + t];
            scl[2 * (r * 1024 + t) + 0] = (int)v.x;
            scl[2 * (r * 1024 + t) + 1] = (int)v.y;
        }
    }
    __syncthreads();

    // Phase 1: per-warp histogram via match_any (leader does plain RMW)
#pragma unroll
    for (int iter = 0; iter < 4; iter++) {
        int c = scl[iter * 1024 + t];
        unsigned mask = __match_any_sync(0xFFFFFFFFu, c);
        if (lane == __ffs(mask) - 1) sW[w * C_ + c] += __popc(mask);
    }
    __syncthreads();

    // Phase 2: column prefix over warps; totals per bin
    if (t < C_) {
        int run = 0;
#pragma unroll
        for (int ww = 0; ww < 32; ww++) {
            int v = sW[ww * C_ + t];
            sW[ww * C_ + t] = run;
            run += v;
        }
        sTot[t] = run;
    }
    __syncthreads();

    // Phase 3: bin starts via single-warp scan (5 bins per lane)
    if (t < 32) {
        int base = t * 5;
        int v[5], s = 0;
#pragma unroll
        for (int i = 0; i < 5; i++) {
            int c = base + i;
            v[i] = (c < C_) ? sTot[c] : 0;
            s += v[i];
        }
        int run = s;
#pragma unroll
        for (int o = 1; o < 32; o <<= 1) {
            int x = __shfl_up_sync(0xFFFFFFFFu, run, o);
            if (t >= o) run += x;
        }
        int acc = run - s;
#pragma unroll
        for (int i = 0; i < 5; i++) {
            int c = base + i;
            if (c < C_) {
                sStart[c] = acc;
                g_starts[bc * (C_ + 1) + c] = acc;
            }
            acc += v[i];
        }
        if (t == 31) g_starts[bc * (C_ + 1) + C_] = N_;
    }
    __syncthreads();

    // cursors = start[c] + per-warp prefix
    for (int i = t; i < 32 * C_; i += 1024) {
        int c = i % C_;
        sW[i] += sStart[c];
    }
    __syncthreads();

    // Phase 4: scatter with match-rank, per-warp cursor (no atomics)
#pragma unroll
    for (int iter = 0; iter < 4; iter++) {
        int n = iter * 1024 + t;
        int c = scl[n];
        unsigned mask = __match_any_sync(0xFFFFFFFFu, c);
        int rank = __popc(mask & ((1u << lane) - 1u));
        int base = sW[w * C_ + c];
        g_order[bc * N_ + base + rank] = n;
        __syncwarp();
        if (lane == __ffs(mask) - 1) sW[w * C_ + c] = base + __popc(mask);
        __syncwarp();
    }
}

// ---------------------------------------------------------------------------
// Kernel 2: per-cluster centers. Warp owns a cluster; 2 members per warp-load
// (float4 lanes), 12-member unroll => 18 LDG.128 in flight. grid (32,8) x 256.
// ---------------------------------------------------------------------------
__global__ void centers_kernel(const float* __restrict__ Q,
                               const float* __restrict__ K,
                               const float* __restrict__ V) {
    int b    = blockIdx.x;
    int bc   = b & 3;
    int wid  = threadIdx.x >> 5;
    int lane = threadIdx.x & 31;
    int half = lane >> 4;
    int dc   = lane & 15;

    const float4* Qb = (const float4*)(Q + (size_t)b * N_ * D_);
    const float4* Kb = (const float4*)(K + (size_t)b * N_ * D_);
    const float4* Vb = (const float4*)(V + (size_t)b * N_ * D_);
    const int* ord = g_order + bc * N_;
    const int* sts = g_starts + bc * (C_ + 1);

    for (int c = blockIdx.y * 8 + wid; c < C_; c += 64) {
        int s0 = sts[c], s1 = sts[c + 1];
        float w = (s1 > s0) ? 1.0f / (float)(s1 - s0) : 0.0f;
        float4 aq = {0.f,0.f,0.f,0.f}, ak = aq, av = aq;

        for (int m = s0; m < s1; m += 12) {
            int   nn[6];
            float mk[6];
#pragma unroll
            for (int p = 0; p < 6; p++) {
                int mm = m + 2 * p + half;
                bool vld = mm < s1;
                nn[p] = __ldg(ord + (vld ? mm : s0));
                mk[p] = vld ? 1.0f : 0.0f;
            }
            float4 q4[6], k4[6], v4[6];
#pragma unroll
            for (int p = 0; p < 6; p++) {
                size_t off = (size_t)nn[p] * 16 + dc;
                q4[p] = Qb[off];
                k4[p] = Kb[off];
                v4[p] = Vb[off];
            }
#pragma unroll
            for (int p = 0; p < 6; p++) {
                aq.x = fmaf(mk[p], q4[p].x, aq.x); aq.y = fmaf(mk[p], q4[p].y, aq.y);
                aq.z = fmaf(mk[p], q4[p].z, aq.z); aq.w = fmaf(mk[p], q4[p].w, aq.w);
                ak.x = fmaf(mk[p], k4[p].x, ak.x); ak.y = fmaf(mk[p], k4[p].y, ak.y);
                ak.z = fmaf(mk[p], k4[p].z, ak.z); ak.w = fmaf(mk[p], k4[p].w, ak.w);
                av.x = fmaf(mk[p], v4[p].x, av.x); av.y = fmaf(mk[p], v4[p].y, av.y);
                av.z = fmaf(mk[p], v4[p].z, av.z); av.w = fmaf(mk[p], v4[p].w, av.w);
            }
        }
        unsigned fm = 0xFFFFFFFFu;
        aq.x += __shfl_xor_sync(fm, aq.x, 16); aq.y += __shfl_xor_sync(fm, aq.y, 16);
        aq.z += __shfl_xor_sync(fm, aq.z, 16); aq.w += __shfl_xor_sync(fm, aq.w, 16);
        ak.x += __shfl_xor_sync(fm, ak.x, 16); ak.y += __shfl_xor_sync(fm, ak.y, 16);
        ak.z += __shfl_xor_sync(fm, ak.z, 16); ak.w += __shfl_xor_sync(fm, ak.w, 16);
        av.x += __shfl_xor_sync(fm, av.x, 16); av.y += __shfl_xor_sync(fm, av.y, 16);
        av.z += __shfl_xor_sync(fm, av.z, 16); av.w += __shfl_xor_sync(fm, av.w, 16);
        if (half == 0) {
            size_t o = (size_t)(b * C_ + c) * 16 + dc;
            ((float4*)g_Qc)[o] = make_float4(aq.x*w, aq.y*w, aq.z*w, aq.w*w);
            ((float4*)g_Kc)[o] = make_float4(ak.x*w, ak.y*w, ak.z*w, ak.w*w);
            ((float4*)g_Vc)[o] = make_float4(av.x*w, av.y*w, av.z*w, av.w*w);
        }
    }
}

// ---------------------------------------------------------------------------
// Kernel 3: centered attention + direct member broadcast. grid (32,9) x 256.
// ---------------------------------------------------------------------------
__global__ void attn_kernel(float* __restrict__ out, float* __restrict__ attn_out) {
    __shared__ __align__(16) float sK[C_ * 68];     // K stride 68; reused for V (stride 64)
    __shared__ __align__(16) float sQt[16 * 68];    // Q tile stride 68; reused as sOut
    __shared__ __align__(16) float sP[16 * 132];    // scores/probs; reused as partial buf
    __shared__ float sCnt[C_];

    int b  = blockIdx.x;
    int bc = b & 3;
    int q0 = blockIdx.y * 16;
    int t  = threadIdx.x;

    const int* sts = g_starts + bc * (C_ + 1);
    const int* ord = g_order + bc * N_;
    for (int k = t; k < C_; k += 256) sCnt[k] = (float)(sts[k + 1] - sts[k]);

    const float* Kc = g_Kc + (size_t)b * C_ * D_;
    for (int i = t; i < C_ * D_; i += 256) {
        int k = i >> 6, d = i & 63;
        sK[k * 68 + d] = Kc[i];
    }
    const float* Qc = g_Qc + (size_t)b * C_ * D_;
    for (int i = t; i < 16 * 64; i += 256) {
        int j = i >> 6, d = i & 63, q = q0 + j;
        sQt[j * 68 + d] = (q < C_) ? Qc[q * 64 + d] : 0.0f;
    }
    __syncthreads();

    // ---- Phase A: scores. thread = (q-quad jp4, k-slot). 4-way q blocking.
    {
        int w      = t >> 5;
        int jp4    = w >> 1;
        int kstart = (t & 31) + 32 * (w & 1);
        const float4* sK4 = (const float4*)sK;
        const float4* sQ4 = (const float4*)sQt;
        float4 a0[4], a1[4];
#pragma unroll
        for (int qi = 0; qi < 4; qi++) { a0[qi] = make_float4(0,0,0,0); a1[qi] = a0[qi]; }
#pragma unroll
        for (int d4 = 0; d4 < 16; d4++) {
            float4 kva = sK4[kstart * 17 + d4];
            float4 kvb = sK4[(kstart + 64) * 17 + d4];
#pragma unroll
            for (int qi = 0; qi < 4; qi++) {
                float4 qv = sQ4[(4 * jp4 + qi) * 17 + d4];
                a0[qi].x = fmaf(qv.x, kva.x, a0[qi].x); a0[qi].y = fmaf(qv.y, kva.y, a0[qi].y);
                a0[qi].z = fmaf(qv.z, kva.z, a0[qi].z); a0[qi].w = fmaf(qv.w, kva.w, a0[qi].w);
                a1[qi].x = fmaf(qv.x, kvb.x, a1[qi].x); a1[qi].y = fmaf(qv.y, kvb.y, a1[qi].y);
                a1[qi].z = fmaf(qv.z, kvb.z, a1[qi].z); a1[qi].w = fmaf(qv.w, kvb.w, a1[qi].w);
            }
        }
#pragma unroll
        for (int qi = 0; qi < 4; qi++) {
            sP[(4 * jp4 + qi) * 132 + kstart]      = (a0[qi].x + a0[qi].y) + (a0[qi].z + a0[qi].w);
            sP[(4 * jp4 + qi) * 132 + kstart + 64] = (a1[qi].x + a1[qi].y) + (a1[qi].z + a1[qi].w);
        }
        if (kstart == 0) {   // epilogue column k=128, float4 path
            float4 a4[4];
#pragma unroll
            for (int qi = 0; qi < 4; qi++) a4[qi] = make_float4(0,0,0,0);
#pragma unroll
            for (int d4 = 0; d4 < 16; d4++) {
                float4 kv = sK4[128 * 17 + d4];
#pragma unroll
                for (int qi = 0; qi < 4; qi++) {
                    float4 qv = sQ4[(4 * jp4 + qi) * 17 + d4];
                    a4[qi].x = fmaf(qv.x, kv.x, a4[qi].x); a4[qi].y = fmaf(qv.y, kv.y, a4[qi].y);
                    a4[qi].z = fmaf(qv.z, kv.z, a4[qi].z); a4[qi].w = fmaf(qv.w, kv.w, a4[qi].w);
                }
            }
#pragma unroll
            for (int qi = 0; qi < 4; qi++)
                sP[(4 * jp4 + qi) * 132 + 128] = (a4[qi].x + a4[qi].y) + (a4[qi].z + a4[qi].w);
        }
    }
    __syncthreads();

    // ---- Softmax with count reweighting: one warp per q row
    {
        int wid = t >> 5, lane = t & 31;
        for (int j = wid; j < 16; j += 8) {
            float* row = &sP[j * 132];
            float v[5];
            float mx = -1e30f;
#pragma unroll
            for (int i = 0; i < 5; i++) {
                int k = lane + 32 * i;
                v[i] = (k < C_) ? row[k] : -1e30f;
                mx = fmaxf(mx, v[i]);
            }
#pragma unroll
            for (int o = 16; o; o >>= 1) mx = fmaxf(mx, __shfl_xor_sync(0xFFFFFFFFu, mx, o));
            float e[5];
            float sum = 0.f;
#pragma unroll
            for (int i = 0; i < 5; i++) {
                int k = lane + 32 * i;
                e[i] = (k < C_) ? __expf(v[i] - mx) * sCnt[k] : 0.0f;
                sum += e[i];
            }
#pragma unroll
            for (int o = 16; o; o >>= 1) sum += __shfl_xor_sync(0xFFFFFFFFu, sum, o);
            float inv = 1.0f / sum;
#pragma unroll
            for (int i = 0; i < 5; i++) {
                int k = lane + 32 * i;
                if (k < C_) row[k] = e[i] * inv;
            }
            if (lane == 0 && (q0 + j) < C_) attn_out[b * C_ + q0 + j] = e[0] * inv;
        }
    }
    __syncthreads();

    // ---- Load V (stride 64) into sK region
    const float* Vc = g_Vc + (size_t)b * C_ * D_;
    for (int i = t; i < C_ * D_; i += 256) sK[i] = Vc[i];
    __syncthreads();

    // ---- Phase B: out = P @ V, then direct broadcast to members.
    {
        int kh2 = t >> 7;
        int jg  = (t >> 4) & 7;
        int dv  = t & 15;
        const float4* sV4 = (const float4*)sK;
        float4 acc0 = make_float4(0,0,0,0), acc1 = acc0;
        for (int k = kh2; k < C_; k += 2) {
            float4 v  = sV4[k * 16 + dv];
            float  p0 = sP[jg * 132 + k];
            float  p1 = sP[(jg + 8) * 132 + k];
            acc0.x = fmaf(p0, v.x, acc0.x); acc0.y = fmaf(p0, v.y, acc0.y);
            acc0.z = fmaf(p0, v.z, acc0.z); acc0.w = fmaf(p0, v.w, acc0.w);
            acc1.x = fmaf(p1, v.x, acc1.x); acc1.y = fmaf(p1, v.y, acc1.y);
            acc1.z = fmaf(p1, v.z, acc1.z); acc1.w = fmaf(p1, v.w, acc1.w);
        }
        __syncthreads();
        float4* part = (float4*)sP;
        part[(kh2 * 16 + jg) * 16 + dv]     = acc0;
        part[(kh2 * 16 + jg + 8) * 16 + dv] = acc1;
        __syncthreads();
        int jj = t >> 4;
        float4 r0 = part[jj * 16 + dv];
        float4 r1 = part[(16 + jj) * 16 + dv];
        float4* sOut4 = (float4*)sQt;
        sOut4[jj * 16 + dv] = make_float4(r0.x + r1.x, r0.y + r1.y, r0.z + r1.z, r0.w + r1.w);
        __syncthreads();

        // Broadcast each cluster's output row to all its members
        int rowSlot = t >> 4;
        for (int j = 0; j < 16; j++) {
            int q = q0 + j;
            if (q >= C_) break;
            int s0 = sts[q], cnt = sts[q + 1] - s0;
            float4 val = sOut4[j * 16 + dv];
            for (int m = rowSlot; m < cnt; m += 16) {
                int n = __ldg(ord + s0 + m);
                ((float4*)(out + ((size_t)b * N_ + n) * D_))[dv] = val;
            }
        }
    }
}

// ---------------------------------------------------------------------------
extern "C" void kernel_launch(void* const* d_in, const int* in_sizes, int n_in,
                              void* d_out, int out_size) {
    const float* Q  = (const float*)d_in[0];
    const float* K  = (const float*)d_in[1];
    const float* V  = (const float*)d_in[2];
    const void*  cl = d_in[3];
    float* out = (float*)d_out;
    float* attn_out = out + (size_t)B_ * N_ * D_;

    sort_kernel<<<BC_, 1024>>>(cl);
    centers_kernel<<<dim3(B_, 8), 256>>>(Q, K, V);
    attn_kernel<<<dim3(B_, (C_ + 15) / 16), 256>>>(out, attn_out);
}

// round 6
// speedup vs baseline: 1.3840x; 1.3840x over previous
#include <cuda_runtime.h>
#include <cuda_bf16.h>

#define B_   32
#define N_   4096
#define D_   64
#define BC_  4
#define C_   129

// Scratch (no allocations allowed)
__device__ __align__(16) int g_order[BC_ * N_];
__device__ __align__(16) int g_starts[BC_ * (C_ + 1)];
__device__ __align__(16) float g_Qc[B_ * C_ * D_];
__device__ __align__(16) float g_Kc[B_ * C_ * D_];
__device__ __align__(16) float g_Vc[B_ * C_ * D_];

// ---------------------------------------------------------------------------
// Kernel 1: dtype detect + counting sort per cluster-batch (4 blocks x 256).
// (R4 version: shared-atomic hist + Hillis-Steele scan + atomic scatter.)
// ---------------------------------------------------------------------------
__global__ void sort_kernel(const void* __restrict__ cl_raw) {
    __shared__ int s_bad;
    __shared__ int scl[N_];
    __shared__ int hist[256];
    __shared__ int scan[256];
    __shared__ int offs[C_];
    int bc = blockIdx.x;
    int t  = threadIdx.x;

    if (t == 0) s_bad = 0;
    hist[t] = 0;
    __syncthreads();
    // int64 view of the buffer's first half == full buffer if data is int32
    const long long* c64 = (const long long*)cl_raw;
    int bad = 0;
    for (int i = t; i < (BC_ * N_) / 2; i += 256) {
        long long v = c64[i];
        if (v < 0 || v >= C_) bad = 1;
    }
    if (bad) atomicOr(&s_bad, 1);
    __syncthreads();

    if (s_bad) {
        const int* c32 = (const int*)cl_raw;
        for (int n = t; n < N_; n += 256) scl[n] = c32[bc * N_ + n];
    } else {
        for (int n = t; n < N_; n += 256) scl[n] = (int)c64[bc * N_ + n];
    }
    __syncthreads();

    for (int n = t; n < N_; n += 256) atomicAdd(&hist[scl[n]], 1);
    __syncthreads();

    // Hillis-Steele inclusive scan over 256 bins
    int val = hist[t];
    scan[t] = val;
    __syncthreads();
#pragma unroll
    for (int off = 1; off < 256; off <<= 1) {
        int v = (t >= off) ? scan[t - off] : 0;
        __syncthreads();
        scan[t] += v;
        __syncthreads();
    }
    int excl = scan[t] - val;
    if (t < C_) {
        g_starts[bc * (C_ + 1) + t] = excl;
        offs[t] = excl;
    }
    if (t == C_ - 1) g_starts[bc * (C_ + 1) + C_] = scan[t];
    __syncthreads();

    for (int n = t; n < N_; n += 256) {
        int p = atomicAdd(&offs[scl[n]], 1);
        g_order[bc * N_ + p] = n;
    }
}

// ---------------------------------------------------------------------------
// Kernel 2: per-cluster centers. Warp owns a cluster; 12-member batches with
// the ord-index loads software-pipelined one batch ahead. grid (32,8) x 256.
// ---------------------------------------------------------------------------
__global__ void __launch_bounds__(256)
centers_kernel(const float* __restrict__ Q,
               const float* __restrict__ K,
               const float* __restrict__ V) {
    int b    = blockIdx.x;
    int bc   = b & 3;
    int wid  = threadIdx.x >> 5;
    int lane = threadIdx.x & 31;
    int half = lane >> 4;
    int dc   = lane & 15;

    const float4* Qb = (const float4*)(Q + (size_t)b * N_ * D_);
    const float4* Kb = (const float4*)(K + (size_t)b * N_ * D_);
    const float4* Vb = (const float4*)(V + (size_t)b * N_ * D_);
    const int* ord = g_order + bc * N_;
    const int* sts = g_starts + bc * (C_ + 1);

    for (int c = blockIdx.y * 8 + wid; c < C_; c += 64) {
        int s0 = sts[c], s1 = sts[c + 1];
        float w = (s1 > s0) ? 1.0f / (float)(s1 - s0) : 0.0f;
        float4 aq = {0.f,0.f,0.f,0.f}, ak = aq, av = aq;

        int   nn[6];
        float mk[6];
#pragma unroll
        for (int p = 0; p < 6; p++) {            // prefetch batch 0
            int mm = s0 + 2 * p + half;
            bool vld = mm < s1;
            nn[p] = __ldg(ord + (vld ? mm : 0));
            mk[p] = vld ? 1.0f : 0.0f;
        }
        for (int m = s0; m < s1; m += 12) {
            int   nn2[6];
            float mk2[6];
#pragma unroll
            for (int p = 0; p < 6; p++) {        // prefetch next batch
                int mm = m + 12 + 2 * p + half;
                bool vld = mm < s1;
                nn2[p] = __ldg(ord + (vld ? mm : 0));
                mk2[p] = vld ? 1.0f : 0.0f;
            }
            float4 q4[6], k4[6], v4[6];
#pragma unroll
            for (int p = 0; p < 6; p++) {
                size_t off = (size_t)nn[p] * 16 + dc;
                q4[p] = Qb[off];
                k4[p] = Kb[off];
                v4[p] = Vb[off];
            }
#pragma unroll
            for (int p = 0; p < 6; p++) {
                aq.x = fmaf(mk[p], q4[p].x, aq.x); aq.y = fmaf(mk[p], q4[p].y, aq.y);
                aq.z = fmaf(mk[p], q4[p].z, aq.z); aq.w = fmaf(mk[p], q4[p].w, aq.w);
                ak.x = fmaf(mk[p], k4[p].x, ak.x); ak.y = fmaf(mk[p], k4[p].y, ak.y);
                ak.z = fmaf(mk[p], k4[p].z, ak.z); ak.w = fmaf(mk[p], k4[p].w, ak.w);
                av.x = fmaf(mk[p], v4[p].x, av.x); av.y = fmaf(mk[p], v4[p].y, av.y);
                av.z = fmaf(mk[p], v4[p].z, av.z); av.w = fmaf(mk[p], v4[p].w, av.w);
            }
#pragma unroll
            for (int p = 0; p < 6; p++) { nn[p] = nn2[p]; mk[p] = mk2[p]; }
        }
        unsigned fm = 0xFFFFFFFFu;
        aq.x += __shfl_xor_sync(fm, aq.x, 16); aq.y += __shfl_xor_sync(fm, aq.y, 16);
        aq.z += __shfl_xor_sync(fm, aq.z, 16); aq.w += __shfl_xor_sync(fm, aq.w, 16);
        ak.x += __shfl_xor_sync(fm, ak.x, 16); ak.y += __shfl_xor_sync(fm, ak.y, 16);
        ak.z += __shfl_xor_sync(fm, ak.z, 16); ak.w += __shfl_xor_sync(fm, ak.w, 16);
        av.x += __shfl_xor_sync(fm, av.x, 16); av.y += __shfl_xor_sync(fm, av.y, 16);
        av.z += __shfl_xor_sync(fm, av.z, 16); av.w += __shfl_xor_sync(fm, av.w, 16);
        if (half == 0) {
            size_t o = (size_t)(b * C_ + c) * 16 + dc;
            ((float4*)g_Qc)[o] = make_float4(aq.x*w, aq.y*w, aq.z*w, aq.w*w);
            ((float4*)g_Kc)[o] = make_float4(ak.x*w, ak.y*w, ak.z*w, ak.w*w);
            ((float4*)g_Vc)[o] = make_float4(av.x*w, av.y*w, av.z*w, av.w*w);
        }
    }
}

// ---------------------------------------------------------------------------
// Kernel 3: centered attention + member broadcast. grid (32,9) x 256.
// Dynamic SMEM layout (floats): sK[C*68] | sV[C*64] | sQt[16*68] | sP[16*132]
//                               | sCnt[C] | (ints) sOrd[1024] | sSt[17]
// ---------------------------------------------------------------------------
#define ATTN_SMEM_FLOATS (C_*68 + C_*64 + 16*68 + 16*132 + C_ + 3)
#define ATTN_SMEM_BYTES  ((ATTN_SMEM_FLOATS + 1024 + 17) * 4)

__global__ void __launch_bounds__(256)
attn_kernel(float* __restrict__ out, float* __restrict__ attn_out) {
    extern __shared__ __align__(16) float smem[];
    float* sK   = smem;                         // stride 68 (17 f4)
    float* sV   = sK + C_ * 68;                 // stride 64 (16 f4)
    float* sQt  = sV + C_ * 64;                 // stride 68; reused as sOut
    float* sP   = sQt + 16 * 68;                // 16 x 132
    float* sCnt = sP + 16 * 132;                // C_ (+3 pad)
    int*   sOrd = (int*)(sCnt + C_ + 3);        // 1024
    int*   sSt  = sOrd + 1024;                  // 17 cluster starts

    int b  = blockIdx.x;
    int bc = b & 3;
    int q0 = blockIdx.y * 16;
    int t  = threadIdx.x;

    const int* sts = g_starts + bc * (C_ + 1);
    const int* ord = g_order + bc * N_;
    for (int k = t; k < C_; k += 256) sCnt[k] = (float)(sts[k + 1] - sts[k]);
    int qe = (q0 + 16 < C_) ? q0 + 16 : C_;
    if (t <= qe - q0) sSt[t] = sts[q0 + t];

    // float4 staging: K (stride 17 f4), V (stride 16 f4), Q tile (stride 17 f4)
    float4* sK4 = (float4*)sK;
    float4* sV4 = (float4*)sV;
    float4* sQ4 = (float4*)sQt;
    const float4* Kc4 = (const float4*)(g_Kc + (size_t)b * C_ * D_);
    const float4* Vc4 = (const float4*)(g_Vc + (size_t)b * C_ * D_);
    const float4* Qc4 = (const float4*)(g_Qc + (size_t)b * C_ * D_);
    for (int i = t; i < C_ * 16; i += 256) {
        int k = i >> 4, d4 = i & 15;
        sK4[k * 17 + d4] = Kc4[i];
        sV4[i] = Vc4[i];
    }
    {
        int j = t >> 4, d4 = t & 15, q = q0 + j;
        sQ4[j * 17 + d4] = (q < C_) ? Qc4[q * 16 + d4] : make_float4(0,0,0,0);
    }
    // stage member indices for this block's clusters
    int m0 = sts[q0];
    int mcount = sts[qe] - m0;
    bool fit = (mcount <= 1024);
    if (fit) for (int i = t; i < mcount; i += 256) sOrd[i] = __ldg(ord + m0 + i);
    __syncthreads();

    // ---- Phase A: scores. thread = (q-quad jp4, k-slot). 4-way q blocking.
    {
        int w      = t >> 5;
        int jp4    = w >> 1;
        int kstart = (t & 31) + 32 * (w & 1);
        float4 a0[4], a1[4];
#pragma unroll
        for (int qi = 0; qi < 4; qi++) { a0[qi] = make_float4(0,0,0,0); a1[qi] = a0[qi]; }
#pragma unroll
        for (int d4 = 0; d4 < 16; d4++) {
            float4 kva = sK4[kstart * 17 + d4];
            float4 kvb = sK4[(kstart + 64) * 17 + d4];
#pragma unroll
            for (int qi = 0; qi < 4; qi++) {
                float4 qv = sQ4[(4 * jp4 + qi) * 17 + d4];
                a0[qi].x = fmaf(qv.x, kva.x, a0[qi].x); a0[qi].y = fmaf(qv.y, kva.y, a0[qi].y);
                a0[qi].z = fmaf(qv.z, kva.z, a0[qi].z); a0[qi].w = fmaf(qv.w, kva.w, a0[qi].w);
                a1[qi].x = fmaf(qv.x, kvb.x, a1[qi].x); a1[qi].y = fmaf(qv.y, kvb.y, a1[qi].y);
                a1[qi].z = fmaf(qv.z, kvb.z, a1[qi].z); a1[qi].w = fmaf(qv.w, kvb.w, a1[qi].w);
            }
        }
#pragma unroll
        for (int qi = 0; qi < 4; qi++) {
            sP[(4 * jp4 + qi) * 132 + kstart]      = (a0[qi].x + a0[qi].y) + (a0[qi].z + a0[qi].w);
            sP[(4 * jp4 + qi) * 132 + kstart + 64] = (a1[qi].x + a1[qi].y) + (a1[qi].z + a1[qi].w);
        }
        if (kstart == 0) {   // epilogue column k=128, float4 path
            float4 a4[4];
#pragma unroll
            for (int qi = 0; qi < 4; qi++) a4[qi] = make_float4(0,0,0,0);
#pragma unroll
            for (int d4 = 0; d4 < 16; d4++) {
                float4 kv = sK4[128 * 17 + d4];
#pragma unroll
                for (int qi = 0; qi < 4; qi++) {
                    float4 qv = sQ4[(4 * jp4 + qi) * 17 + d4];
                    a4[qi].x = fmaf(qv.x, kv.x, a4[qi].x); a4[qi].y = fmaf(qv.y, kv.y, a4[qi].y);
                    a4[qi].z = fmaf(qv.z, kv.z, a4[qi].z); a4[qi].w = fmaf(qv.w, kv.w, a4[qi].w);
                }
            }
#pragma unroll
            for (int qi = 0; qi < 4; qi++)
                sP[(4 * jp4 + qi) * 132 + 128] = (a4[qi].x + a4[qi].y) + (a4[qi].z + a4[qi].w);
        }
    }
    __syncthreads();

    // ---- Softmax with count reweighting: one warp per q row
    {
        int wid = t >> 5, lane = t & 31;
        for (int j = wid; j < 16; j += 8) {
            float* row = &sP[j * 132];
            float v[5];
            float mx = -1e30f;
#pragma unroll
            for (int i = 0; i < 5; i++) {
                int k = lane + 32 * i;
                v[i] = (k < C_) ? row[k] : -1e30f;
                mx = fmaxf(mx, v[i]);
            }
#pragma unroll
            for (int o = 16; o; o >>= 1) mx = fmaxf(mx, __shfl_xor_sync(0xFFFFFFFFu, mx, o));
            float e[5];
            float sum = 0.f;
#pragma unroll
            for (int i = 0; i < 5; i++) {
                int k = lane + 32 * i;
                e[i] = (k < C_) ? __expf(v[i] - mx) * sCnt[k] : 0.0f;
                sum += e[i];
            }
#pragma unroll
            for (int o = 16; o; o >>= 1) sum += __shfl_xor_sync(0xFFFFFFFFu, sum, o);
            float inv = 1.0f / sum;
#pragma unroll
            for (int i = 0; i < 5; i++) {
                int k = lane + 32 * i;
                if (k < C_) row[k] = e[i] * inv;
            }
            if (lane == 0 && (q0 + j) < C_) attn_out[b * C_ + q0 + j] = e[0] * inv;
        }
    }
    __syncthreads();

    // ---- Phase B: out = P @ V, then direct broadcast to members.
    {
        int kh2 = t >> 7;
        int jg  = (t >> 4) & 7;
        int dv  = t & 15;
        float4 acc0 = make_float4(0,0,0,0), acc1 = acc0;
        for (int k = kh2; k < C_; k += 2) {
            float4 v  = sV4[k * 16 + dv];
            float  p0 = sP[jg * 132 + k];
            float  p1 = sP[(jg + 8) * 132 + k];
            acc0.x = fmaf(p0, v.x, acc0.x); acc0.y = fmaf(p0, v.y, acc0.y);
            acc0.z = fmaf(p0, v.z, acc0.z); acc0.w = fmaf(p0, v.w, acc0.w);
            acc1.x = fmaf(p1, v.x, acc1.x); acc1.y = fmaf(p1, v.y, acc1.y);
            acc1.z = fmaf(p1, v.z, acc1.z); acc1.w = fmaf(p1, v.w, acc1.w);
        }
        __syncthreads();
        float4* part = (float4*)sP;
        part[(kh2 * 16 + jg) * 16 + dv]     = acc0;
        part[(kh2 * 16 + jg + 8) * 16 + dv] = acc1;
        __syncthreads();
        int jj = t >> 4;
        float4 r0 = part[jj * 16 + dv];
        float4 r1 = part[(16 + jj) * 16 + dv];
        float4* sOut4 = (float4*)sQt;    // Q tile is dead now
        sOut4[jj * 16 + dv] = make_float4(r0.x + r1.x, r0.y + r1.y, r0.z + r1.z, r0.w + r1.w);
        __syncthreads();

        // Broadcast each cluster's output row to all its members
        int rowSlot = t >> 4;
        int nj = qe - q0;
        if (fit) {
            for (int j = 0; j < nj; j++) {
                int s0l = sSt[j] - m0, cnt = sSt[j + 1] - sSt[j];
                float4 val = sOut4[j * 16 + dv];
                for (int m = rowSlot; m < cnt; m += 16) {
                    int n = sOrd[s0l + m];
                    ((float4*)(out + ((size_t)b * N_ + n) * D_))[dv] = val;
                }
            }
        } else {
            for (int j = 0; j < nj; j++) {
                int s0g = sSt[j], cnt = sSt[j + 1] - s0g;
                float4 val = sOut4[j * 16 + dv];
                for (int m = rowSlot; m < cnt; m += 16) {
                    int n = __ldg(ord + s0g + m);
                    ((float4*)(out + ((size_t)b * N_ + n) * D_))[dv] = val;
                }
            }
        }
    }
}

// ---------------------------------------------------------------------------
extern "C" void kernel_launch(void* const* d_in, const int* in_sizes, int n_in,
                              void* d_out, int out_size) {
    const float* Q  = (const float*)d_in[0];
    const float* K  = (const float*)d_in[1];
    const float* V  = (const float*)d_in[2];
    const void*  cl = d_in[3];
    float* out = (float*)d_out;
    float* attn_out = out + (size_t)B_ * N_ * D_;

    cudaFuncSetAttribute(attn_kernel, cudaFuncAttributeMaxDynamicSharedMemorySize,
                         ATTN_SMEM_BYTES);

    sort_kernel<<<BC_, 256>>>(cl);
    centers_kernel<<<dim3(B_, 8), 256>>>(Q, K, V);
    attn_kernel<<<dim3(B_, (C_ + 15) / 16), 256, ATTN_SMEM_BYTES>>>(out, attn_out);
}

// round 7
// speedup vs baseline: 1.5019x; 1.0852x over previous
#include <cuda_runtime.h>
#include <cuda_bf16.h>

#define B_   32
#define N_   4096
#define D_   64
#define BC_  4
#define C_   129

// Scratch (no allocations allowed)
__device__ __align__(16) int g_order[BC_ * N_];
__device__ __align__(16) int g_starts[BC_ * (C_ + 1)];
__device__ __align__(16) float g_Qc[B_ * C_ * D_];
__device__ __align__(16) float g_Kc[B_ * C_ * D_];
__device__ __align__(16) float g_Vc[B_ * C_ * D_];

// ---------------------------------------------------------------------------
// Kernel 1: dtype detect + counting sort per cluster-batch. grid 4 x 1024.
// Shared-atomic histogram + 256-wide Hillis-Steele scan + atomic scatter.
// ---------------------------------------------------------------------------
__global__ void __launch_bounds__(1024)
sort_kernel(const void* __restrict__ cl_raw) {
    __shared__ int s_bad;
    __shared__ int scl[N_];
    __shared__ int hist[256];
    __shared__ int scan[256];
    __shared__ int offs[C_];
    int bc = blockIdx.x;
    int t  = threadIdx.x;

    if (t == 0) s_bad = 0;
    if (t < 256) hist[t] = 0;
    __syncthreads();

    // dtype check on the int64 words overlaying OUR int32 slice:
    // if data is int32, each word packs two random labels -> fails range test.
    {
        const long long* slice64 =
            (const long long*)((const int*)cl_raw + (size_t)bc * N_);
        int bad = 0;
#pragma unroll
        for (int r = 0; r < 2; r++) {
            long long v = slice64[r * 1024 + t];
            if (v < 0 || v >= C_) bad = 1;
        }
        if (bad) s_bad = 1;   // benign race, write-only
    }
    __syncthreads();

    if (s_bad) {
        const int4* c32v = (const int4*)((const int*)cl_raw + (size_t)bc * N_);
        int4 v = c32v[t];
        scl[4 * t + 0] = v.x; scl[4 * t + 1] = v.y;
        scl[4 * t + 2] = v.z; scl[4 * t + 3] = v.w;
    } else {
        const longlong2* c64v =
            (const longlong2*)((const long long*)cl_raw + (size_t)bc * N_);
#pragma unroll
        for (int r = 0; r < 2; r++) {
            longlong2 v = c64v[r * 1024 + t];
            scl[2 * (r * 1024 + t) + 0] = (int)v.x;
            scl[2 * (r * 1024 + t) + 1] = (int)v.y;
        }
    }
    __syncthreads();

#pragma unroll
    for (int r = 0; r < 4; r++) atomicAdd(&hist[scl[r * 1024 + t]], 1);
    __syncthreads();

    // Hillis-Steele inclusive scan over 256 bins (first 256 threads)
    int val = 0;
    if (t < 256) {
        val = hist[t];
        scan[t] = val;
    }
    __syncthreads();
#pragma unroll
    for (int off = 1; off < 256; off <<= 1) {
        int v = 0;
        if (t < 256 && t >= off) v = scan[t - off];
        __syncthreads();
        if (t < 256) scan[t] += v;
        __syncthreads();
    }
    if (t < C_) {
        int excl = scan[t] - val;
        g_starts[bc * (C_ + 1) + t] = excl;
        offs[t] = excl;
    }
    if (t == C_ - 1) g_starts[bc * (C_ + 1) + C_] = scan[t];
    __syncthreads();

#pragma unroll
    for (int r = 0; r < 4; r++) {
        int n = r * 1024 + t;
        int p = atomicAdd(&offs[scl[n]], 1);
        g_order[bc * N_ + p] = n;
    }
}

// ---------------------------------------------------------------------------
// Kernel 2: per-cluster centers. Warp owns a cluster; 12-member batches with
// the ord-index loads software-pipelined one batch ahead. grid (32,16) x 256.
// ---------------------------------------------------------------------------
__global__ void __launch_bounds__(256)
centers_kernel(const float* __restrict__ Q,
               const float* __restrict__ K,
               const float* __restrict__ V) {
    int b    = blockIdx.x;
    int bc   = b & 3;
    int wid  = threadIdx.x >> 5;
    int lane = threadIdx.x & 31;
    int half = lane >> 4;
    int dc   = lane & 15;

    const float4* Qb = (const float4*)(Q + (size_t)b * N_ * D_);
    const float4* Kb = (const float4*)(K + (size_t)b * N_ * D_);
    const float4* Vb = (const float4*)(V + (size_t)b * N_ * D_);
    const int* ord = g_order + bc * N_;
    const int* sts = g_starts + bc * (C_ + 1);

    for (int c = blockIdx.y * 8 + wid; c < C_; c += 128) {
        int s0 = sts[c], s1 = sts[c + 1];
        float w = (s1 > s0) ? 1.0f / (float)(s1 - s0) : 0.0f;
        float4 aq = {0.f,0.f,0.f,0.f}, ak = aq, av = aq;

        int   nn[6];
        float mk[6];
#pragma unroll
        for (int p = 0; p < 6; p++) {            // prefetch batch 0
            int mm = s0 + 2 * p + half;
            bool vld = mm < s1;
            nn[p] = __ldg(ord + (vld ? mm : 0));
            mk[p] = vld ? 1.0f : 0.0f;
        }
        for (int m = s0; m < s1; m += 12) {
            int   nn2[6];
            float mk2[6];
#pragma unroll
            for (int p = 0; p < 6; p++) {        // prefetch next batch
                int mm = m + 12 + 2 * p + half;
                bool vld = mm < s1;
                nn2[p] = __ldg(ord + (vld ? mm : 0));
                mk2[p] = vld ? 1.0f : 0.0f;
            }
            float4 q4[6], k4[6], v4[6];
#pragma unroll
            for (int p = 0; p < 6; p++) {
                size_t off = (size_t)nn[p] * 16 + dc;
                q4[p] = Qb[off];
                k4[p] = Kb[off];
                v4[p] = Vb[off];
            }
#pragma unroll
            for (int p = 0; p < 6; p++) {
                aq.x = fmaf(mk[p], q4[p].x, aq.x); aq.y = fmaf(mk[p], q4[p].y, aq.y);
                aq.z = fmaf(mk[p], q4[p].z, aq.z); aq.w = fmaf(mk[p], q4[p].w, aq.w);
                ak.x = fmaf(mk[p], k4[p].x, ak.x); ak.y = fmaf(mk[p], k4[p].y, ak.y);
                ak.z = fmaf(mk[p], k4[p].z, ak.z); ak.w = fmaf(mk[p], k4[p].w, ak.w);
                av.x = fmaf(mk[p], v4[p].x, av.x); av.y = fmaf(mk[p], v4[p].y, av.y);
                av.z = fmaf(mk[p], v4[p].z, av.z); av.w = fmaf(mk[p], v4[p].w, av.w);
            }
#pragma unroll
            for (int p = 0; p < 6; p++) { nn[p] = nn2[p]; mk[p] = mk2[p]; }
        }
        unsigned fm = 0xFFFFFFFFu;
        aq.x += __shfl_xor_sync(fm, aq.x, 16); aq.y += __shfl_xor_sync(fm, aq.y, 16);
        aq.z += __shfl_xor_sync(fm, aq.z, 16); aq.w += __shfl_xor_sync(fm, aq.w, 16);
        ak.x += __shfl_xor_sync(fm, ak.x, 16); ak.y += __shfl_xor_sync(fm, ak.y, 16);
        ak.z += __shfl_xor_sync(fm, ak.z, 16); ak.w += __shfl_xor_sync(fm, ak.w, 16);
        av.x += __shfl_xor_sync(fm, av.x, 16); av.y += __shfl_xor_sync(fm, av.y, 16);
        av.z += __shfl_xor_sync(fm, av.z, 16); av.w += __shfl_xor_sync(fm, av.w, 16);
        if (half == 0) {
            size_t o = (size_t)(b * C_ + c) * 16 + dc;
            ((float4*)g_Qc)[o] = make_float4(aq.x*w, aq.y*w, aq.z*w, aq.w*w);
            ((float4*)g_Kc)[o] = make_float4(ak.x*w, ak.y*w, ak.z*w, ak.w*w);
            ((float4*)g_Vc)[o] = make_float4(av.x*w, av.y*w, av.z*w, av.w*w);
        }
    }
}

// ---------------------------------------------------------------------------
// Kernel 3: centered attention + member broadcast. grid (32,9) x 256.
// Dynamic SMEM layout (floats): sK[C*68] | sV[C*64] | sQt[16*68] | sP[16*132]
//                               | sCnt[C] | (ints) sOrd[1024] | sSt[17]
// ---------------------------------------------------------------------------
#define ATTN_SMEM_FLOATS (C_*68 + C_*64 + 16*68 + 16*132 + C_ + 3)
#define ATTN_SMEM_BYTES  ((ATTN_SMEM_FLOATS + 1024 + 17) * 4)

__global__ void __launch_bounds__(256)
attn_kernel(float* __restrict__ out, float* __restrict__ attn_out) {
    extern __shared__ __align__(16) float smem[];
    float* sK   = smem;
    float* sV   = sK + C_ * 68;
    float* sQt  = sV + C_ * 64;
    float* sP   = sQt + 16 * 68;
    float* sCnt = sP + 16 * 132;
    int*   sOrd = (int*)(sCnt + C_ + 3);
    int*   sSt  = sOrd + 1024;

    int b  = blockIdx.x;
    int bc = b & 3;
    int q0 = blockIdx.y * 16;
    int t  = threadIdx.x;

    const int* sts = g_starts + bc * (C_ + 1);
    const int* ord = g_order + bc * N_;
    for (int k = t; k < C_; k += 256) sCnt[k] = (float)(sts[k + 1] - sts[k]);
    int qe = (q0 + 16 < C_) ? q0 + 16 : C_;
    if (t <= qe - q0) sSt[t] = sts[q0 + t];

    float4* sK4 = (float4*)sK;
    float4* sV4 = (float4*)sV;
    float4* sQ4 = (float4*)sQt;
    const float4* Kc4 = (const float4*)(g_Kc + (size_t)b * C_ * D_);
    const float4* Vc4 = (const float4*)(g_Vc + (size_t)b * C_ * D_);
    const float4* Qc4 = (const float4*)(g_Qc + (size_t)b * C_ * D_);
    for (int i = t; i < C_ * 16; i += 256) {
        int k = i >> 4, d4 = i & 15;
        sK4[k * 17 + d4] = Kc4[i];
        sV4[i] = Vc4[i];
    }
    {
        int j = t >> 4, d4 = t & 15, q = q0 + j;
        sQ4[j * 17 + d4] = (q < C_) ? Qc4[q * 16 + d4] : make_float4(0,0,0,0);
    }
    int m0 = sts[q0];
    int mcount = sts[qe] - m0;
    bool fit = (mcount <= 1024);
    if (fit) for (int i = t; i < mcount; i += 256) sOrd[i] = __ldg(ord + m0 + i);
    __syncthreads();

    // ---- Phase A: scores. thread = (q-quad jp4, k-slot). 4-way q blocking.
    {
        int w      = t >> 5;
        int jp4    = w >> 1;
        int kstart = (t & 31) + 32 * (w & 1);
        float4 a0[4], a1[4];
#pragma unroll
        for (int qi = 0; qi < 4; qi++) { a0[qi] = make_float4(0,0,0,0); a1[qi] = a0[qi]; }
#pragma unroll
        for (int d4 = 0; d4 < 16; d4++) {
            float4 kva = sK4[kstart * 17 + d4];
            float4 kvb = sK4[(kstart + 64) * 17 + d4];
#pragma unroll
            for (int qi = 0; qi < 4; qi++) {
                float4 qv = sQ4[(4 * jp4 + qi) * 17 + d4];
                a0[qi].x = fmaf(qv.x, kva.x, a0[qi].x); a0[qi].y = fmaf(qv.y, kva.y, a0[qi].y);
                a0[qi].z = fmaf(qv.z, kva.z, a0[qi].z); a0[qi].w = fmaf(qv.w, kva.w, a0[qi].w);
                a1[qi].x = fmaf(qv.x, kvb.x, a1[qi].x); a1[qi].y = fmaf(qv.y, kvb.y, a1[qi].y);
                a1[qi].z = fmaf(qv.z, kvb.z, a1[qi].z); a1[qi].w = fmaf(qv.w, kvb.w, a1[qi].w);
            }
        }
#pragma unroll
        for (int qi = 0; qi < 4; qi++) {
            sP[(4 * jp4 + qi) * 132 + kstart]      = (a0[qi].x + a0[qi].y) + (a0[qi].z + a0[qi].w);
            sP[(4 * jp4 + qi) * 132 + kstart + 64] = (a1[qi].x + a1[qi].y) + (a1[qi].z + a1[qi].w);
        }
        if (kstart == 0) {   // epilogue column k=128
            float4 a4[4];
#pragma unroll
            for (int qi = 0; qi < 4; qi++) a4[qi] = make_float4(0,0,0,0);
#pragma unroll
            for (int d4 = 0; d4 < 16; d4++) {
                float4 kv = sK4[128 * 17 + d4];
#pragma unroll
                for (int qi = 0; qi < 4; qi++) {
                    float4 qv = sQ4[(4 * jp4 + qi) * 17 + d4];
                    a4[qi].x = fmaf(qv.x, kv.x, a4[qi].x); a4[qi].y = fmaf(qv.y, kv.y, a4[qi].y);
                    a4[qi].z = fmaf(qv.z, kv.z, a4[qi].z); a4[qi].w = fmaf(qv.w, kv.w, a4[qi].w);
                }
            }
#pragma unroll
            for (int qi = 0; qi < 4; qi++)
                sP[(4 * jp4 + qi) * 132 + 128] = (a4[qi].x + a4[qi].y) + (a4[qi].z + a4[qi].w);
        }
    }
    __syncthreads();

    // ---- Softmax with count reweighting: one warp per q row
    {
        int wid = t >> 5, lane = t & 31;
        for (int j = wid; j < 16; j += 8) {
            float* row = &sP[j * 132];
            float v[5];
            float mx = -1e30f;
#pragma unroll
            for (int i = 0; i < 5; i++) {
                int k = lane + 32 * i;
                v[i] = (k < C_) ? row[k] : -1e30f;
                mx = fmaxf(mx, v[i]);
            }
#pragma unroll
            for (int o = 16; o; o >>= 1) mx = fmaxf(mx, __shfl_xor_sync(0xFFFFFFFFu, mx, o));
            float e[5];
            float sum = 0.f;
#pragma unroll
            for (int i = 0; i < 5; i++) {
                int k = lane + 32 * i;
                e[i] = (k < C_) ? __expf(v[i] - mx) * sCnt[k] : 0.0f;
                sum += e[i];
            }
#pragma unroll
            for (int o = 16; o; o >>= 1) sum += __shfl_xor_sync(0xFFFFFFFFu, sum, o);
            float inv = 1.0f / sum;
#pragma unroll
            for (int i = 0; i < 5; i++) {
                int k = lane + 32 * i;
                if (k < C_) row[k] = e[i] * inv;
            }
            if (lane == 0 && (q0 + j) < C_) attn_out[b * C_ + q0 + j] = e[0] * inv;
        }
    }
    __syncthreads();

    // ---- Phase B: out = P @ V, then direct broadcast to members.
    {
        int kh2 = t >> 7;
        int jg  = (t >> 4) & 7;
        int dv  = t & 15;
        float4 acc0 = make_float4(0,0,0,0), acc1 = acc0;
        for (int k = kh2; k < C_; k += 2) {
            float4 v  = sV4[k * 16 + dv];
            float  p0 = sP[jg * 132 + k];
            float  p1 = sP[(jg + 8) * 132 + k];
            acc0.x = fmaf(p0, v.x, acc0.x); acc0.y = fmaf(p0, v.y, acc0.y);
            acc0.z = fmaf(p0, v.z, acc0.z); acc0.w = fmaf(p0, v.w, acc0.w);
            acc1.x = fmaf(p1, v.x, acc1.x); acc1.y = fmaf(p1, v.y, acc1.y);
            acc1.z = fmaf(p1, v.z, acc1.z); acc1.w = fmaf(p1, v.w, acc1.w);
        }
        __syncthreads();
        float4* part = (float4*)sP;
        part[(kh2 * 16 + jg) * 16 + dv]     = acc0;
        part[(kh2 * 16 + jg + 8) * 16 + dv] = acc1;
        __syncthreads();
        int jj = t >> 4;
        float4 r0 = part[jj * 16 + dv];
        float4 r1 = part[(16 + jj) * 16 + dv];
        float4* sOut4 = (float4*)sQt;
        sOut4[jj * 16 + dv] = make_float4(r0.x + r1.x, r0.y + r1.y, r0.z + r1.z, r0.w + r1.w);
        __syncthreads();

        int rowSlot = t >> 4;
        int dv2 = t & 15;
        int nj = qe - q0;
        if (fit) {
            for (int j = 0; j < nj; j++) {
                int s0l = sSt[j] - m0, cnt = sSt[j + 1] - sSt[j];
                float4 val = sOut4[j * 16 + dv2];
                for (int m = rowSlot; m < cnt; m += 16) {
                    int n = sOrd[s0l + m];
                    ((float4*)(out + ((size_t)b * N_ + n) * D_))[dv2] = val;
                }
            }
        } else {
            for (int j = 0; j < nj; j++) {
                int s0g = sSt[j], cnt = sSt[j + 1] - s0g;
                float4 val = sOut4[j * 16 + dv2];
                for (int m = rowSlot; m < cnt; m += 16) {
                    int n = __ldg(ord + s0g + m);
                    ((float4*)(out + ((size_t)b * N_ + n) * D_))[dv2] = val;
                }
            }
        }
    }
}

// ---------------------------------------------------------------------------
extern "C" void kernel_launch(void* const* d_in, const int* in_sizes, int n_in,
                              void* d_out, int out_size) {
    const float* Q  = (const float*)d_in[0];
    const float* K  = (const float*)d_in[1];
    const float* V  = (const float*)d_in[2];
    const void*  cl = d_in[3];
    float* out = (float*)d_out;
    float* attn_out = out + (size_t)B_ * N_ * D_;

    cudaFuncSetAttribute(attn_kernel, cudaFuncAttributeMaxDynamicSharedMemorySize,
                         ATTN_SMEM_BYTES);

    sort_kernel<<<BC_, 1024>>>(cl);
    centers_kernel<<<dim3(B_, 16), 256>>>(Q, K, V);
    attn_kernel<<<dim3(B_, (C_ + 15) / 16), 256, ATTN_SMEM_BYTES>>>(out, attn_out);
}

// round 8
// speedup vs baseline: 1.5151x; 1.0088x over previous
#include <cuda_runtime.h>
#include <cuda_bf16.h>

#define B_   32
#define N_   4096
#define D_   64
#define BC_  4
#define C_   129

// Scratch (no allocations allowed)
__device__ __align__(16) int g_order[BC_ * N_];
__device__ __align__(16) int g_starts[BC_ * (C_ + 1)];
__device__ __align__(16) float g_Qc[B_ * C_ * D_];
__device__ __align__(16) float g_Kc[B_ * C_ * D_];
__device__ __align__(16) float g_Vc[B_ * C_ * D_];

// ---------------------------------------------------------------------------
// Kernel 1: dtype detect + counting sort per cluster-batch. grid 4 x 1024.
// 4 barriers total: sampled dtype check, shared-atomic hist, single-warp
// shfl scan, atomic scatter.
// ---------------------------------------------------------------------------
__global__ void __launch_bounds__(1024)
sort_kernel(const void* __restrict__ cl_raw) {
    __shared__ int s_bad;
    __shared__ int scl[N_];
    __shared__ int hist[C_];
    __shared__ int offs[C_];
    int bc = blockIdx.x;
    int t  = threadIdx.x;

    // dtype sample: 32 int64 words at buffer head (labels of bc 0 either way).
    // int32 data packs two random labels per word -> fails range test.
    if (t < 32) {
        long long v = __ldg((const long long*)cl_raw + t);
        unsigned bad = __ballot_sync(0xFFFFFFFFu, v < 0 || v >= C_);
        if (t == 0) s_bad = (bad != 0);
    }
    if (t < C_) hist[t] = 0;
    __syncthreads();

    if (s_bad) {
        const int4* c32v = (const int4*)((const int*)cl_raw + (size_t)bc * N_);
        int4 v = c32v[t];
        scl[4 * t + 0] = v.x; scl[4 * t + 1] = v.y;
        scl[4 * t + 2] = v.z; scl[4 * t + 3] = v.w;
    } else {
        const longlong2* c64v =
            (const longlong2*)((const long long*)cl_raw + (size_t)bc * N_);
#pragma unroll
        for (int r = 0; r < 2; r++) {
            longlong2 v = c64v[r * 1024 + t];
            scl[2 * (r * 1024 + t) + 0] = (int)v.x;
            scl[2 * (r * 1024 + t) + 1] = (int)v.y;
        }
    }
    __syncthreads();

#pragma unroll
    for (int r = 0; r < 4; r++) atomicAdd(&hist[scl[r * 1024 + t]], 1);
    __syncthreads();

    // single-warp exclusive scan over 129 bins: 5 bins/lane + shfl prefix
    if (t < 32) {
        int base = t * 5;
        int v[5], s = 0;
#pragma unroll
        for (int i = 0; i < 5; i++) {
            int c = base + i;
            v[i] = (c < C_) ? hist[c] : 0;
            s += v[i];
        }
        int run = s;
#pragma unroll
        for (int o = 1; o < 32; o <<= 1) {
            int x = __shfl_up_sync(0xFFFFFFFFu, run, o);
            if (t >= o) run += x;
        }
        int acc = run - s;   // exclusive prefix of this lane's 5-bin group
#pragma unroll
        for (int i = 0; i < 5; i++) {
            int c = base + i;
            if (c < C_) {
                offs[c] = acc;
                g_starts[bc * (C_ + 1) + c] = acc;
            }
            acc += v[i];
        }
        if (t == 31) g_starts[bc * (C_ + 1) + C_] = N_;
    }
    __syncthreads();

#pragma unroll
    for (int r = 0; r < 4; r++) {
        int n = r * 1024 + t;
        int p = atomicAdd(&offs[scl[n]], 1);
        g_order[bc * N_ + p] = n;
    }
}

// ---------------------------------------------------------------------------
// Kernel 2: per-cluster centers. Warp owns a cluster; 8-member batches (2 per
// warp-load, float4 lanes), ord prefetched one batch ahead. 3 blocks/SM.
// grid (32,16) x 256.
// ---------------------------------------------------------------------------
__global__ void __launch_bounds__(256, 3)
centers_kernel(const float* __restrict__ Q,
               const float* __restrict__ K,
               const float* __restrict__ V) {
    int b    = blockIdx.x;
    int bc   = b & 3;
    int wid  = threadIdx.x >> 5;
    int lane = threadIdx.x & 31;
    int half = lane >> 4;
    int dc   = lane & 15;

    const float4* Qb = (const float4*)(Q + (size_t)b * N_ * D_);
    const float4* Kb = (const float4*)(K + (size_t)b * N_ * D_);
    const float4* Vb = (const float4*)(V + (size_t)b * N_ * D_);
    const int* ord = g_order + bc * N_;
    const int* sts = g_starts + bc * (C_ + 1);

    for (int c = blockIdx.y * 8 + wid; c < C_; c += 128) {
        int s0 = sts[c], s1 = sts[c + 1];
        float w = (s1 > s0) ? 1.0f / (float)(s1 - s0) : 0.0f;
        float4 aq = {0.f,0.f,0.f,0.f}, ak = aq, av = aq;

        int   nn[4];
        float mk[4];
#pragma unroll
        for (int p = 0; p < 4; p++) {            // prefetch batch 0
            int mm = s0 + 2 * p + half;
            bool vld = mm < s1;
            nn[p] = __ldg(ord + (vld ? mm : 0));
            mk[p] = vld ? 1.0f : 0.0f;
        }
        for (int m = s0; m < s1; m += 8) {
            int   nn2[4];
            float mk2[4];
#pragma unroll
            for (int p = 0; p < 4; p++) {        // prefetch next batch
                int mm = m + 8 + 2 * p + half;
                bool vld = mm < s1;
                nn2[p] = __ldg(ord + (vld ? mm : 0));
                mk2[p] = vld ? 1.0f : 0.0f;
            }
            float4 q4[4], k4[4], v4[4];
#pragma unroll
            for (int p = 0; p < 4; p++) {
                size_t off = (size_t)nn[p] * 16 + dc;
                q4[p] = Qb[off];
                k4[p] = Kb[off];
                v4[p] = Vb[off];
            }
#pragma unroll
            for (int p = 0; p < 4; p++) {
                aq.x = fmaf(mk[p], q4[p].x, aq.x); aq.y = fmaf(mk[p], q4[p].y, aq.y);
                aq.z = fmaf(mk[p], q4[p].z, aq.z); aq.w = fmaf(mk[p], q4[p].w, aq.w);
                ak.x = fmaf(mk[p], k4[p].x, ak.x); ak.y = fmaf(mk[p], k4[p].y, ak.y);
                ak.z = fmaf(mk[p], k4[p].z, ak.z); ak.w = fmaf(mk[p], k4[p].w, ak.w);
                av.x = fmaf(mk[p], v4[p].x, av.x); av.y = fmaf(mk[p], v4[p].y, av.y);
                av.z = fmaf(mk[p], v4[p].z, av.z); av.w = fmaf(mk[p], v4[p].w, av.w);
            }
#pragma unroll
            for (int p = 0; p < 4; p++) { nn[p] = nn2[p]; mk[p] = mk2[p]; }
        }
        unsigned fm = 0xFFFFFFFFu;
        aq.x += __shfl_xor_sync(fm, aq.x, 16); aq.y += __shfl_xor_sync(fm, aq.y, 16);
        aq.z += __shfl_xor_sync(fm, aq.z, 16); aq.w += __shfl_xor_sync(fm, aq.w, 16);
        ak.x += __shfl_xor_sync(fm, ak.x, 16); ak.y += __shfl_xor_sync(fm, ak.y, 16);
        ak.z += __shfl_xor_sync(fm, ak.z, 16); ak.w += __shfl_xor_sync(fm, ak.w, 16);
        av.x += __shfl_xor_sync(fm, av.x, 16); av.y += __shfl_xor_sync(fm, av.y, 16);
        av.z += __shfl_xor_sync(fm, av.z, 16); av.w += __shfl_xor_sync(fm, av.w, 16);
        if (half == 0) {
            size_t o = (size_t)(b * C_ + c) * 16 + dc;
            ((float4*)g_Qc)[o] = make_float4(aq.x*w, aq.y*w, aq.z*w, aq.w*w);
            ((float4*)g_Kc)[o] = make_float4(ak.x*w, ak.y*w, ak.z*w, ak.w*w);
            ((float4*)g_Vc)[o] = make_float4(av.x*w, av.y*w, av.z*w, av.w*w);
        }
    }
}

// ---------------------------------------------------------------------------
// Kernel 3: centered attention + member broadcast. grid (32,9) x 256.
// Dynamic SMEM layout (floats): sK[C*68] | sV[C*64] | sQt[16*68] | sP[16*132]
//                               | sCnt[C] | (ints) sOrd[1024] | sSt[17]
// ---------------------------------------------------------------------------
#define ATTN_SMEM_FLOATS (C_*68 + C_*64 + 16*68 + 16*132 + C_ + 3)
#define ATTN_SMEM_BYTES  ((ATTN_SMEM_FLOATS + 1024 + 17) * 4)

__global__ void __launch_bounds__(256)
attn_kernel(float* __restrict__ out, float* __restrict__ attn_out) {
    extern __shared__ __align__(16) float smem[];
    float* sK   = smem;
    float* sV   = sK + C_ * 68;
    float* sQt  = sV + C_ * 64;
    float* sP   = sQt + 16 * 68;
    float* sCnt = sP + 16 * 132;
    int*   sOrd = (int*)(sCnt + C_ + 3);
    int*   sSt  = sOrd + 1024;

    int b  = blockIdx.x;
    int bc = b & 3;
    int q0 = blockIdx.y * 16;
    int t  = threadIdx.x;

    const int* sts = g_starts + bc * (C_ + 1);
    const int* ord = g_order + bc * N_;
    for (int k = t; k < C_; k += 256) sCnt[k] = (float)(sts[k + 1] - sts[k]);
    int qe = (q0 + 16 < C_) ? q0 + 16 : C_;
    if (t <= qe - q0) sSt[t] = sts[q0 + t];

    float4* sK4 = (float4*)sK;
    float4* sV4 = (float4*)sV;
    float4* sQ4 = (float4*)sQt;
    const float4* Kc4 = (const float4*)(g_Kc + (size_t)b * C_ * D_);
    const float4* Vc4 = (const float4*)(g_Vc + (size_t)b * C_ * D_);
    const float4* Qc4 = (const float4*)(g_Qc + (size_t)b * C_ * D_);
    for (int i = t; i < C_ * 16; i += 256) {
        int k = i >> 4, d4 = i & 15;
        sK4[k * 17 + d4] = Kc4[i];
        sV4[i] = Vc4[i];
    }
    {
        int j = t >> 4, d4 = t & 15, q = q0 + j;
        sQ4[j * 17 + d4] = (q < C_) ? Qc4[q * 16 + d4] : make_float4(0,0,0,0);
    }
    int m0 = sts[q0];
    int mcount = sts[qe] - m0;
    bool fit = (mcount <= 1024);
    if (fit) for (int i = t; i < mcount; i += 256) sOrd[i] = __ldg(ord + m0 + i);
    __syncthreads();

    // ---- Phase A: scores. thread = (q-quad jp4, k-slot). 4-way q blocking.
    {
        int w      = t >> 5;
        int jp4    = w >> 1;
        int kstart = (t & 31) + 32 * (w & 1);
        float4 a0[4], a1[4];
#pragma unroll
        for (int qi = 0; qi < 4; qi++) { a0[qi] = make_float4(0,0,0,0); a1[qi] = a0[qi]; }
#pragma unroll
        for (int d4 = 0; d4 < 16; d4++) {
            float4 kva = sK4[kstart * 17 + d4];
            float4 kvb = sK4[(kstart + 64) * 17 + d4];
#pragma unroll
            for (int qi = 0; qi < 4; qi++) {
                float4 qv = sQ4[(4 * jp4 + qi) * 17 + d4];
                a0[qi].x = fmaf(qv.x, kva.x, a0[qi].x); a0[qi].y = fmaf(qv.y, kva.y, a0[qi].y);
                a0[qi].z = fmaf(qv.z, kva.z, a0[qi].z); a0[qi].w = fmaf(qv.w, kva.w, a0[qi].w);
                a1[qi].x = fmaf(qv.x, kvb.x, a1[qi].x); a1[qi].y = fmaf(qv.y, kvb.y, a1[qi].y);
                a1[qi].z = fmaf(qv.z, kvb.z, a1[qi].z); a1[qi].w = fmaf(qv.w, kvb.w, a1[qi].w);
            }
        }
#pragma unroll
        for (int qi = 0; qi < 4; qi++) {
            sP[(4 * jp4 + qi) * 132 + kstart]      = (a0[qi].x + a0[qi].y) + (a0[qi].z + a0[qi].w);
            sP[(4 * jp4 + qi) * 132 + kstart + 64] = (a1[qi].x + a1[qi].y) + (a1[qi].z + a1[qi].w);
        }
        if (kstart == 0) {   // epilogue column k=128
            float4 a4[4];
#pragma unroll
            for (int qi = 0; qi < 4; qi++) a4[qi] = make_float4(0,0,0,0);
#pragma unroll
            for (int d4 = 0; d4 < 16; d4++) {
                float4 kv = sK4[128 * 17 + d4];
#pragma unroll
                for (int qi = 0; qi < 4; qi++) {
                    float4 qv = sQ4[(4 * jp4 + qi) * 17 + d4];
                    a4[qi].x = fmaf(qv.x, kv.x, a4[qi].x); a4[qi].y = fmaf(qv.y, kv.y, a4[qi].y);
                    a4[qi].z = fmaf(qv.z, kv.z, a4[qi].z); a4[qi].w = fmaf(qv.w, kv.w, a4[qi].w);
                }
            }
#pragma unroll
            for (int qi = 0; qi < 4; qi++)
                sP[(4 * jp4 + qi) * 132 + 128] = (a4[qi].x + a4[qi].y) + (a4[qi].z + a4[qi].w);
        }
    }
    __syncthreads();

    // ---- Softmax with count reweighting: one warp per q row
    {
        int wid = t >> 5, lane = t & 31;
        for (int j = wid; j < 16; j += 8) {
            float* row = &sP[j * 132];
            float v[5];
            float mx = -1e30f;
#pragma unroll
            for (int i = 0; i < 5; i++) {
                int k = lane + 32 * i;
                v[i] = (k < C_) ? row[k] : -1e30f;
                mx = fmaxf(mx, v[i]);
            }
#pragma unroll
            for (int o = 16; o; o >>= 1) mx = fmaxf(mx, __shfl_xor_sync(0xFFFFFFFFu, mx, o));
            float e[5];
            float sum = 0.f;
#pragma unroll
            for (int i = 0; i < 5; i++) {
                int k = lane + 32 * i;
                e[i] = (k < C_) ? __expf(v[i] - mx) * sCnt[k] : 0.0f;
                sum += e[i];
            }
#pragma unroll
            for (int o = 16; o; o >>= 1) sum += __shfl_xor_sync(0xFFFFFFFFu, sum, o);
            float inv = 1.0f / sum;
#pragma unroll
            for (int i = 0; i < 5; i++) {
                int k = lane + 32 * i;
                if (k < C_) row[k] = e[i] * inv;
            }
            if (lane == 0 && (q0 + j) < C_) attn_out[b * C_ + q0 + j] = e[0] * inv;
        }
    }
    __syncthreads();

    // ---- Phase B: out = P @ V, then direct broadcast to members.
    {
        int kh2 = t >> 7;
        int jg  = (t >> 4) & 7;
        int dv  = t & 15;
        float4 acc0 = make_float4(0,0,0,0), acc1 = acc0;
        for (int k = kh2; k < C_; k += 2) {
            float4 v  = sV4[k * 16 + dv];
            float  p0 = sP[jg * 132 + k];
            float  p1 = sP[(jg + 8) * 132 + k];
            acc0.x = fmaf(p0, v.x, acc0.x); acc0.y = fmaf(p0, v.y, acc0.y);
            acc0.z = fmaf(p0, v.z, acc0.z); acc0.w = fmaf(p0, v.w, acc0.w);
            acc1.x = fmaf(p1, v.x, acc1.x); acc1.y = fmaf(p1, v.y, acc1.y);
            acc1.z = fmaf(p1, v.z, acc1.z); acc1.w = fmaf(p1, v.w, acc1.w);
        }
        __syncthreads();
        float4* part = (float4*)sP;
        part[(kh2 * 16 + jg) * 16 + dv]     = acc0;
        part[(kh2 * 16 + jg + 8) * 16 + dv] = acc1;
        __syncthreads();
        int jj = t >> 4;
        float4 r0 = part[jj * 16 + dv];
        float4 r1 = part[(16 + jj) * 16 + dv];
        float4* sOut4 = (float4*)sQt;
        sOut4[jj * 16 + dv] = make_float4(r0.x + r1.x, r0.y + r1.y, r0.z + r1.z, r0.w + r1.w);
        __syncthreads();

        int rowSlot = t >> 4;
        int dv2 = t & 15;
        int nj = qe - q0;
        if (fit) {
            for (int j = 0; j < nj; j++) {
                int s0l = sSt[j] - m0, cnt = sSt[j + 1] - sSt[j];
                float4 val = sOut4[j * 16 + dv2];
                for (int m = rowSlot; m < cnt; m += 16) {
                    int n = sOrd[s0l + m];
                    ((float4*)(out + ((size_t)b * N_ + n) * D_))[dv2] = val;
                }
            }
        } else {
            for (int j = 0; j < nj; j++) {
                int s0g = sSt[j], cnt = sSt[j + 1] - s0g;
                float4 val = sOut4[j * 16 + dv2];
                for (int m = rowSlot; m < cnt; m += 16) {
                    int n = __ldg(ord + s0g + m);
                    ((float4*)(out + ((size_t)b * N_ + n) * D_))[dv2] = val;
                }
            }
        }
    }
}

// ---------------------------------------------------------------------------
extern "C" void kernel_launch(void* const* d_in, const int* in_sizes, int n_in,
                              void* d_out, int out_size) {
    const float* Q  = (const float*)d_in[0];
    const float* K  = (const float*)d_in[1];
    const float* V  = (const float*)d_in[2];
    const void*  cl = d_in[3];
    float* out = (float*)d_out;
    float* attn_out = out + (size_t)B_ * N_ * D_;

    cudaFuncSetAttribute(attn_kernel, cudaFuncAttributeMaxDynamicSharedMemorySize,
                         ATTN_SMEM_BYTES);

    sort_kernel<<<BC_, 1024>>>(cl);
    centers_kernel<<<dim3(B_, 16), 256>>>(Q, K, V);
    attn_kernel<<<dim3(B_, (C_ + 15) / 16), 256, ATTN_SMEM_BYTES>>>(out, attn_out);
}

// round 9
// speedup vs baseline: 1.5429x; 1.0184x over previous
#include <cuda_runtime.h>
#include <cuda_bf16.h>

#define B_   32
#define N_   4096
#define D_   64
#define BC_  4
#define C_   129
#define NSL_ 8                 // slices per cluster-batch
#define SL_  (N_ / NSL_)       // 512 labels per slice

// Scratch (no allocations allowed)
__device__ __align__(16) int g_lab[BC_ * N_];
__device__ __align__(16) int g_parthist[BC_ * NSL_ * C_];
__device__ __align__(16) int g_order[BC_ * N_];
__device__ __align__(16) int g_starts[BC_ * (C_ + 1)];
__device__ __align__(16) float g_Qc[B_ * C_ * D_];
__device__ __align__(16) float g_Kc[B_ * C_ * D_];
__device__ __align__(16) float g_Vc[B_ * C_ * D_];

// ---------------------------------------------------------------------------
// Kernel 1a: decode labels + per-slice histogram. grid (NSL_, BC_) x 256.
// ---------------------------------------------------------------------------
__global__ void __launch_bounds__(256)
hist_kernel(const void* __restrict__ cl_raw) {
    __shared__ int hist[C_];
    __shared__ int s_bad;
    int blk = blockIdx.x;
    int bc  = blockIdx.y;
    int t   = threadIdx.x;

    // dtype sample: 32 int64 words at buffer head. int32 data packs two
    // random labels per word -> range test fails with prob ~1.
    if (t < 32) {
        long long v = __ldg((const long long*)cl_raw + t);
        unsigned bad = __ballot_sync(0xFFFFFFFFu, v < 0 || v >= C_);
        if (t == 0) s_bad = (bad != 0);
    }
    if (t < C_) hist[t] = 0;
    __syncthreads();

    int base = bc * N_ + blk * SL_;
    int lab[2];
    if (s_bad) {
        const int* c32 = (const int*)cl_raw;
        lab[0] = c32[base + t];
        lab[1] = c32[base + t + 256];
    } else {
        const long long* c64 = (const long long*)cl_raw;
        lab[0] = (int)c64[base + t];
        lab[1] = (int)c64[base + t + 256];
    }
    g_lab[base + t]       = lab[0];
    g_lab[base + t + 256] = lab[1];
    atomicAdd(&hist[lab[0]], 1);
    atomicAdd(&hist[lab[1]], 1);
    __syncthreads();

    if (t < C_) g_parthist[(bc * NSL_ + blk) * C_ + t] = hist[t];
}

// ---------------------------------------------------------------------------
// Kernel 1b: combine partial hists, scan, scatter own slice.
// grid (NSL_, BC_) x 256.
// ---------------------------------------------------------------------------
__global__ void __launch_bounds__(256)
scatter_kernel() {
    __shared__ int sTot[C_];
    __shared__ int sPre[C_];
    __shared__ int sStart[C_];
    __shared__ int offs[C_];
    int blk = blockIdx.x;
    int bc  = blockIdx.y;
    int t   = threadIdx.x;

    if (t < C_) {
        const int* ph = g_parthist + bc * NSL_ * C_ + t;
        int pre = 0, tot = 0;
#pragma unroll
        for (int s = 0; s < NSL_; s++) {
            int v = __ldg(ph + s * C_);
            if (s < blk) pre += v;
            tot += v;
        }
        sPre[t] = pre;
        sTot[t] = tot;
    }
    __syncthreads();

    // single-warp exclusive scan over 129 bins
    if (t < 32) {
        int base = t * 5;
        int v[5], s = 0;
#pragma unroll
        for (int i = 0; i < 5; i++) {
            int c = base + i;
            v[i] = (c < C_) ? sTot[c] : 0;
            s += v[i];
        }
        int run = s;
#pragma unroll
        for (int o = 1; o < 32; o <<= 1) {
            int x = __shfl_up_sync(0xFFFFFFFFu, run, o);
            if (t >= o) run += x;
        }
        int acc = run - s;
#pragma unroll
        for (int i = 0; i < 5; i++) {
            int c = base + i;
            if (c < C_) {
                sStart[c] = acc;
                if (blk == 0) g_starts[bc * (C_ + 1) + c] = acc;
            }
            acc += v[i];
        }
        if (t == 31 && blk == 0) g_starts[bc * (C_ + 1) + C_] = N_;
    }
    __syncthreads();

    if (t < C_) offs[t] = sStart[t] + sPre[t];
    __syncthreads();

    int base = bc * N_ + blk * SL_;
#pragma unroll
    for (int r = 0; r < 2; r++) {
        int i = r * 256 + t;
        int lab = g_lab[base + i];
        int p = atomicAdd(&offs[lab], 1);
        g_order[bc * N_ + p] = blk * SL_ + i;
    }
}

// ---------------------------------------------------------------------------
// Kernel 2: per-cluster centers. Warp owns a cluster; 8-member batches (2 per
// warp-load, float4 lanes), ord prefetched one batch ahead. 3 blocks/SM.
// grid (32,16) x 256.
// ---------------------------------------------------------------------------
__global__ void __launch_bounds__(256, 3)
centers_kernel(const float* __restrict__ Q,
               const float* __restrict__ K,
               const float* __restrict__ V) {
    int b    = blockIdx.x;
    int bc   = b & 3;
    int wid  = threadIdx.x >> 5;
    int lane = threadIdx.x & 31;
    int half = lane >> 4;
    int dc   = lane & 15;

    const float4* Qb = (const float4*)(Q + (size_t)b * N_ * D_);
    const float4* Kb = (const float4*)(K + (size_t)b * N_ * D_);
    const float4* Vb = (const float4*)(V + (size_t)b * N_ * D_);
    const int* ord = g_order + bc * N_;
    const int* sts = g_starts + bc * (C_ + 1);

    for (int c = blockIdx.y * 8 + wid; c < C_; c += 128) {
        int s0 = sts[c], s1 = sts[c + 1];
        float w = (s1 > s0) ? 1.0f / (float)(s1 - s0) : 0.0f;
        float4 aq = {0.f,0.f,0.f,0.f}, ak = aq, av = aq;

        int   nn[4];
        float mk[4];
#pragma unroll
        for (int p = 0; p < 4; p++) {
            int mm = s0 + 2 * p + half;
            bool vld = mm < s1;
            nn[p] = __ldg(ord + (vld ? mm : 0));
            mk[p] = vld ? 1.0f : 0.0f;
        }
        for (int m = s0; m < s1; m += 8) {
            int   nn2[4];
            float mk2[4];
#pragma unroll
            for (int p = 0; p < 4; p++) {
                int mm = m + 8 + 2 * p + half;
                bool vld = mm < s1;
                nn2[p] = __ldg(ord + (vld ? mm : 0));
                mk2[p] = vld ? 1.0f : 0.0f;
            }
            float4 q4[4], k4[4], v4[4];
#pragma unroll
            for (int p = 0; p < 4; p++) {
                size_t off = (size_t)nn[p] * 16 + dc;
                q4[p] = Qb[off];
                k4[p] = Kb[off];
                v4[p] = Vb[off];
            }
#pragma unroll
            for (int p = 0; p < 4; p++) {
                aq.x = fmaf(mk[p], q4[p].x, aq.x); aq.y = fmaf(mk[p], q4[p].y, aq.y);
                aq.z = fmaf(mk[p], q4[p].z, aq.z); aq.w = fmaf(mk[p], q4[p].w, aq.w);
                ak.x = fmaf(mk[p], k4[p].x, ak.x); ak.y = fmaf(mk[p], k4[p].y, ak.y);
                ak.z = fmaf(mk[p], k4[p].z, ak.z); ak.w = fmaf(mk[p], k4[p].w, ak.w);
                av.x = fmaf(mk[p], v4[p].x, av.x); av.y = fmaf(mk[p], v4[p].y, av.y);
                av.z = fmaf(mk[p], v4[p].z, av.z); av.w = fmaf(mk[p], v4[p].w, av.w);
            }
#pragma unroll
            for (int p = 0; p < 4; p++) { nn[p] = nn2[p]; mk[p] = mk2[p]; }
        }
        unsigned fm = 0xFFFFFFFFu;
        aq.x += __shfl_xor_sync(fm, aq.x, 16); aq.y += __shfl_xor_sync(fm, aq.y, 16);
        aq.z += __shfl_xor_sync(fm, aq.z, 16); aq.w += __shfl_xor_sync(fm, aq.w, 16);
        ak.x += __shfl_xor_sync(fm, ak.x, 16); ak.y += __shfl_xor_sync(fm, ak.y, 16);
        ak.z += __shfl_xor_sync(fm, ak.z, 16); ak.w += __shfl_xor_sync(fm, ak.w, 16);
        av.x += __shfl_xor_sync(fm, av.x, 16); av.y += __shfl_xor_sync(fm, av.y, 16);
        av.z += __shfl_xor_sync(fm, av.z, 16); av.w += __shfl_xor_sync(fm, av.w, 16);
        if (half == 0) {
            size_t o = (size_t)(b * C_ + c) * 16 + dc;
            ((float4*)g_Qc)[o] = make_float4(aq.x*w, aq.y*w, aq.z*w, aq.w*w);
            ((float4*)g_Kc)[o] = make_float4(ak.x*w, ak.y*w, ak.z*w, ak.w*w);
            ((float4*)g_Vc)[o] = make_float4(av.x*w, av.y*w, av.z*w, av.w*w);
        }
    }
}

// ---------------------------------------------------------------------------
// Kernel 3: centered attention + member broadcast. grid (32,9) x 256.
// Dynamic SMEM layout (floats): sK[C*68] | sV[C*64] | sQt[16*68] | sP[16*132]
//                               | sCnt[C] | (ints) sOrd[1024] | sSt[17]
// ---------------------------------------------------------------------------
#define ATTN_SMEM_FLOATS (C_*68 + C_*64 + 16*68 + 16*132 + C_ + 3)
#define ATTN_SMEM_BYTES  ((ATTN_SMEM_FLOATS + 1024 + 17) * 4)

__global__ void __launch_bounds__(256)
attn_kernel(float* __restrict__ out, float* __restrict__ attn_out) {
    extern __shared__ __align__(16) float smem[];
    float* sK   = smem;
    float* sV   = sK + C_ * 68;
    float* sQt  = sV + C_ * 64;
    float* sP   = sQt + 16 * 68;
    float* sCnt = sP + 16 * 132;
    int*   sOrd = (int*)(sCnt + C_ + 3);
    int*   sSt  = sOrd + 1024;

    int b  = blockIdx.x;
    int bc = b & 3;
    int q0 = blockIdx.y * 16;
    int t  = threadIdx.x;

    const int* sts = g_starts + bc * (C_ + 1);
    const int* ord = g_order + bc * N_;
    for (int k = t; k < C_; k += 256) sCnt[k] = (float)(sts[k + 1] - sts[k]);
    int qe = (q0 + 16 < C_) ? q0 + 16 : C_;
    if (t <= qe - q0) sSt[t] = sts[q0 + t];

    float4* sK4 = (float4*)sK;
    float4* sV4 = (float4*)sV;
    float4* sQ4 = (float4*)sQt;
    const float4* Kc4 = (const float4*)(g_Kc + (size_t)b * C_ * D_);
    const float4* Vc4 = (const float4*)(g_Vc + (size_t)b * C_ * D_);
    const float4* Qc4 = (const float4*)(g_Qc + (size_t)b * C_ * D_);
    for (int i = t; i < C_ * 16; i += 256) {
        int k = i >> 4, d4 = i & 15;
        sK4[k * 17 + d4] = Kc4[i];
        sV4[i] = Vc4[i];
    }
    {
        int j = t >> 4, d4 = t & 15, q = q0 + j;
        sQ4[j * 17 + d4] = (q < C_) ? Qc4[q * 16 + d4] : make_float4(0,0,0,0);
    }
    int m0 = sts[q0];
    int mcount = sts[qe] - m0;
    bool fit = (mcount <= 1024);
    if (fit) for (int i = t; i < mcount; i += 256) sOrd[i] = __ldg(ord + m0 + i);
    __syncthreads();

    // ---- Phase A: scores. thread = (q-quad jp4, k-slot). 4-way q blocking.
    {
        int w      = t >> 5;
        int jp4    = w >> 1;
        int kstart = (t & 31) + 32 * (w & 1);
        float4 a0[4], a1[4];
#pragma unroll
        for (int qi = 0; qi < 4; qi++) { a0[qi] = make_float4(0,0,0,0); a1[qi] = a0[qi]; }
#pragma unroll
        for (int d4 = 0; d4 < 16; d4++) {
            float4 kva = sK4[kstart * 17 + d4];
            float4 kvb = sK4[(kstart + 64) * 17 + d4];
#pragma unroll
            for (int qi = 0; qi < 4; qi++) {
                float4 qv = sQ4[(4 * jp4 + qi) * 17 + d4];
                a0[qi].x = fmaf(qv.x, kva.x, a0[qi].x); a0[qi].y = fmaf(qv.y, kva.y, a0[qi].y);
                a0[qi].z = fmaf(qv.z, kva.z, a0[qi].z); a0[qi].w = fmaf(qv.w, kva.w, a0[qi].w);
                a1[qi].x = fmaf(qv.x, kvb.x, a1[qi].x); a1[qi].y = fmaf(qv.y, kvb.y, a1[qi].y);
                a1[qi].z = fmaf(qv.z, kvb.z, a1[qi].z); a1[qi].w = fmaf(qv.w, kvb.w, a1[qi].w);
            }
        }
#pragma unroll
        for (int qi = 0; qi < 4; qi++) {
            sP[(4 * jp4 + qi) * 132 + kstart]      = (a0[qi].x + a0[qi].y) + (a0[qi].z + a0[qi].w);
            sP[(4 * jp4 + qi) * 132 + kstart + 64] = (a1[qi].x + a1[qi].y) + (a1[qi].z + a1[qi].w);
        }
        if (kstart == 0) {   // epilogue column k=128
            float4 a4[4];
#pragma unroll
            for (int qi = 0; qi < 4; qi++) a4[qi] = make_float4(0,0,0,0);
#pragma unroll
            for (int d4 = 0; d4 < 16; d4++) {
                float4 kv = sK4[128 * 17 + d4];
#pragma unroll
                for (int qi = 0; qi < 4; qi++) {
                    float4 qv = sQ4[(4 * jp4 + qi) * 17 + d4];
                    a4[qi].x = fmaf(qv.x, kv.x, a4[qi].x); a4[qi].y = fmaf(qv.y, kv.y, a4[qi].y);
                    a4[qi].z = fmaf(qv.z, kv.z, a4[qi].z); a4[qi].w = fmaf(qv.w, kv.w, a4[qi].w);
                }
            }
#pragma unroll
            for (int qi = 0; qi < 4; qi++)
                sP[(4 * jp4 + qi) * 132 + 128] = (a4[qi].x + a4[qi].y) + (a4[qi].z + a4[qi].w);
        }
    }
    __syncthreads();

    // ---- Softmax with count reweighting: one warp per q row
    {
        int wid = t >> 5, lane = t & 31;
        for (int j = wid; j < 16; j += 8) {
            float* row = &sP[j * 132];
            float v[5];
            float mx = -1e30f;
#pragma unroll
            for (int i = 0; i < 5; i++) {
                int k = lane + 32 * i;
                v[i] = (k < C_) ? row[k] : -1e30f;
                mx = fmaxf(mx, v[i]);
            }
#pragma unroll
            for (int o = 16; o; o >>= 1) mx = fmaxf(mx, __shfl_xor_sync(0xFFFFFFFFu, mx, o));
            float e[5];
            float sum = 0.f;
#pragma unroll
            for (int i = 0; i < 5; i++) {
                int k = lane + 32 * i;
                e[i] = (k < C_) ? __expf(v[i] - mx) * sCnt[k] : 0.0f;
                sum += e[i];
            }
#pragma unroll
            for (int o = 16; o; o >>= 1) sum += __shfl_xor_sync(0xFFFFFFFFu, sum, o);
            float inv = 1.0f / sum;
#pragma unroll
            for (int i = 0; i < 5; i++) {
                int k = lane + 32 * i;
                if (k < C_) row[k] = e[i] * inv;
            }
            if (lane == 0 && (q0 + j) < C_) attn_out[b * C_ + q0 + j] = e[0] * inv;
        }
    }
    __syncthreads();

    // ---- Phase B: out = P @ V, then direct broadcast to members.
    {
        int kh2 = t >> 7;
        int jg  = (t >> 4) & 7;
        int dv  = t & 15;
        float4 acc0 = make_float4(0,0,0,0), acc1 = acc0;
        for (int k = kh2; k < C_; k += 2) {
            float4 v  = sV4[k * 16 + dv];
            float  p0 = sP[jg * 132 + k];
            float  p1 = sP[(jg + 8) * 132 + k];
            acc0.x = fmaf(p0, v.x, acc0.x); acc0.y = fmaf(p0, v.y, acc0.y);
            acc0.z = fmaf(p0, v.z, acc0.z); acc0.w = fmaf(p0, v.w, acc0.w);
            acc1.x = fmaf(p1, v.x, acc1.x); acc1.y = fmaf(p1, v.y, acc1.y);
            acc1.z = fmaf(p1, v.z, acc1.z); acc1.w = fmaf(p1, v.w, acc1.w);
        }
        __syncthreads();
        float4* part = (float4*)sP;
        part[(kh2 * 16 + jg) * 16 + dv]     = acc0;
        part[(kh2 * 16 + jg + 8) * 16 + dv] = acc1;
        __syncthreads();
        int jj = t >> 4;
        float4 r0 = part[jj * 16 + dv];
        float4 r1 = part[(16 + jj) * 16 + dv];
        float4* sOut4 = (float4*)sQt;
        sOut4[jj * 16 + dv] = make_float4(r0.x + r1.x, r0.y + r1.y, r0.z + r1.z, r0.w + r1.w);
        __syncthreads();

        int rowSlot = t >> 4;
        int dv2 = t & 15;
        int nj = qe - q0;
        if (fit) {
            for (int j = 0; j < nj; j++) {
                int s0l = sSt[j] - m0, cnt = sSt[j + 1] - sSt[j];
                float4 val = sOut4[j * 16 + dv2];
                for (int m = rowSlot; m < cnt; m += 16) {
                    int n = sOrd[s0l + m];
                    ((float4*)(out + ((size_t)b * N_ + n) * D_))[dv2] = val;
                }
            }
        } else {
            for (int j = 0; j < nj; j++) {
                int s0g = sSt[j], cnt = sSt[j + 1] - s0g;
                float4 val = sOut4[j * 16 + dv2];
                for (int m = rowSlot; m < cnt; m += 16) {
                    int n = __ldg(ord + s0g + m);
                    ((float4*)(out + ((size_t)b * N_ + n) * D_))[dv2] = val;
                }
            }
        }
    }
}

// ---------------------------------------------------------------------------
extern "C" void kernel_launch(void* const* d_in, const int* in_sizes, int n_in,
                              void* d_out, int out_size) {
    const float* Q  = (const float*)d_in[0];
    const float* K  = (const float*)d_in[1];
    const float* V  = (const float*)d_in[2];
    const void*  cl = d_in[3];
    float* out = (float*)d_out;
    float* attn_out = out + (size_t)B_ * N_ * D_;

    cudaFuncSetAttribute(attn_kernel, cudaFuncAttributeMaxDynamicSharedMemorySize,
                         ATTN_SMEM_BYTES);

    hist_kernel<<<dim3(NSL_, BC_), 256>>>(cl);
    scatter_kernel<<<dim3(NSL_, BC_), 256>>>();
    centers_kernel<<<dim3(B_, 16), 256>>>(Q, K, V);
    attn_kernel<<<dim3(B_, (C_ + 15) / 16), 256, ATTN_SMEM_BYTES>>>(out, attn_out);
}